// round 16
// baseline (speedup 1.0000x reference)
#include <cuda_runtime.h>
#include <cuda_bf16.h>
#include <cstdint>
#include <cmath>

#define B_TOTAL 1024
#define H 256
#define HP 128

typedef unsigned int u32;

// ---------------------------------------------------------------------------
// Scratch (static device arrays — allocation-free)
// ---------------------------------------------------------------------------
__device__ __nv_bfloat16 g_x3h[B_TOTAL * HP];          // 256 KB
__device__ __nv_bfloat16 g_x3l[B_TOTAL * HP];          // 256 KB
__device__ float         g_g1[B_TOTAL * H];            // 1 MB

__device__ __forceinline__ u32 smem_u32_of(const void* p) {
    u32 a;
    asm("{ .reg .u64 t; cvta.to.shared.u64 t, %1; cvt.u32.u64 %0, t; }"
        : "=r"(a) : "l"(p));
    return a;
}

__device__ __forceinline__ void ldsm4(u32* r, u32 addr) {
    asm volatile("ldmatrix.sync.aligned.m8n8.x4.shared.b16 {%0,%1,%2,%3}, [%4];"
                 : "=r"(r[0]), "=r"(r[1]), "=r"(r[2]), "=r"(r[3]) : "r"(addr));
}

__device__ __forceinline__ void mma_bf16(float* c, const u32* a, const u32* b) {
    asm volatile(
        "mma.sync.aligned.m16n8k16.row.col.f32.bf16.bf16.f32 "
        "{%0,%1,%2,%3}, {%4,%5,%6,%7}, {%8,%9}, {%0,%1,%2,%3};"
        : "+f"(c[0]), "+f"(c[1]), "+f"(c[2]), "+f"(c[3])
        : "r"(a[0]), "r"(a[1]), "r"(a[2]), "r"(a[3]), "r"(b[0]), "r"(b[1]));
}

__device__ __forceinline__ void cp16(u32 dst, const void* src) {
    const size_t gs = __cvta_generic_to_global(src);
    asm volatile("cp.async.ca.shared.global [%0], [%1], 16;"
                 :: "r"(dst), "l"(gs) : "memory");
}
#define CP_COMMIT() asm volatile("cp.async.commit_group;" ::: "memory")
#define CP_WAIT(n)  asm volatile("cp.async.wait_group %0;" :: "n"(n) : "memory")

__device__ __forceinline__ u32 pack_bf16x2(__nv_bfloat16 a, __nv_bfloat16 b) {
    __nv_bfloat162 t(a, b);
    return *reinterpret_cast<u32*>(&t);
}

// ---------------------------------------------------------------------------
// Kernel 1: MLP head -> x3 split hi/lo bf16
// ---------------------------------------------------------------------------
__global__ __launch_bounds__(128) void mlp_head_kernel(
    const float* __restrict__ h0, const float* __restrict__ ht,
    const float* __restrict__ cin,
    const float* __restrict__ w1, const float* __restrict__ w2,
    const float* __restrict__ w3)
{
    __shared__ float hs[4][H];
    __shared__ float xa[4][HP];
    __shared__ float xb[4][HP];

    const int b0  = blockIdx.x * 4;
    const int tid = threadIdx.x;
    const float cc = fminf(fmaxf(cin[0], 0.0f), 1.0f);

    for (int i = tid; i < 4 * H; i += 128) {
        const int bb = i >> 8, hh = i & (H - 1);
        const int g = (b0 + bb) * H + hh;
        hs[bb][hh] = cc * h0[g] + (1.0f - cc) * ht[g];
    }
    __syncthreads();

    {
        float acc[4] = {0.f, 0.f, 0.f, 0.f};
        const float4* wrow = reinterpret_cast<const float4*>(w1 + tid * H);
#pragma unroll
        for (int c = 0; c < H / 4; c++) {
            const float4 w = __ldg(wrow + c);
#pragma unroll
            for (int bb = 0; bb < 4; bb++) {
                const float4 hv = *reinterpret_cast<const float4*>(&hs[bb][c * 4]);
                acc[bb] = fmaf(w.x, hv.x, fmaf(w.y, hv.y,
                          fmaf(w.z, hv.z, fmaf(w.w, hv.w, acc[bb]))));
            }
        }
#pragma unroll
        for (int bb = 0; bb < 4; bb++) xa[bb][tid] = tanhf(acc[bb]);
    }
    __syncthreads();
    {
        float acc[4] = {0.f, 0.f, 0.f, 0.f};
        const float4* wrow = reinterpret_cast<const float4*>(w2 + tid * HP);
#pragma unroll
        for (int c = 0; c < HP / 4; c++) {
            const float4 w = __ldg(wrow + c);
#pragma unroll
            for (int bb = 0; bb < 4; bb++) {
                const float4 hv = *reinterpret_cast<const float4*>(&xa[bb][c * 4]);
                acc[bb] = fmaf(w.x, hv.x, fmaf(w.y, hv.y,
                          fmaf(w.z, hv.z, fmaf(w.w, hv.w, acc[bb]))));
            }
        }
#pragma unroll
        for (int bb = 0; bb < 4; bb++) xb[bb][tid] = tanhf(acc[bb]);
    }
    __syncthreads();
    {
        float acc[4] = {0.f, 0.f, 0.f, 0.f};
        const float4* wrow = reinterpret_cast<const float4*>(w3 + tid * HP);
#pragma unroll
        for (int c = 0; c < HP / 4; c++) {
            const float4 w = __ldg(wrow + c);
#pragma unroll
            for (int bb = 0; bb < 4; bb++) {
                const float4 hv = *reinterpret_cast<const float4*>(&xb[bb][c * 4]);
                acc[bb] = fmaf(w.x, hv.x, fmaf(w.y, hv.y,
                          fmaf(w.z, hv.z, fmaf(w.w, hv.w, acc[bb]))));
            }
        }
#pragma unroll
        for (int bb = 0; bb < 4; bb++) {
            const float v = tanhf(acc[bb]);
            const __nv_bfloat16 hv = __float2bfloat16(v);
            const int o = (b0 + bb) * HP + tid;
            g_x3h[o] = hv;
            g_x3l[o] = __float2bfloat16(v - __bfloat162float(hv));
        }
    }
}

// ---------------------------------------------------------------------------
// Kernel 2: W-resident HMMA hyper-GEMM + fold, bf16x3 split precision.
// Grid (256 kk, 4 bsplit), 512 threads / 16 warps. Each CTA:
//   - loads its W_kk tile [256h x 128r] fp32 ONCE, splits to bf16 hi/lo smem
//   - loops over 4 b-tiles of 64 rows (its 256-row split): cp.async
//     double-buffered A (x3 hi/lo), D[64b x 256h] via 3 split HMMA products,
//     folds with vec -> out.
// Warp (bgrp=wid&3, hgrp=wid>>2) owns 16b x 64h: acc[8][4] (32 regs).
// ---------------------------------------------------------------------------
#define TSTRIDE 272                 // bytes per tile row (128 bf16 + pad)
#define OFF_BH  0
#define OFF_BL  (256 * TSTRIDE)                 // 69632
#define OFF_AST (2 * 256 * TSTRIDE)             // 139264
#define A_STAGE (2 * 64 * TSTRIDE)              // 34816 (hi+lo)
#define OFF_RED (OFF_AST + 2 * A_STAGE)         // 208896
#define SMEM_TOTAL (OFF_RED + 64 * 4 * 4)       // 209920 bytes
#define NIT 4

template <bool APPLY_TANH>
__global__ __launch_bounds__(512, 1) void hyper_mma_kernel(
    const float* __restrict__ W,     // phase half, fp32 [H*H, HP]
    const float* __restrict__ vec,   // [B, H]
    float* __restrict__ outp)        // [B, H]
{
    extern __shared__ __align__(16) char smem[];
    const u32 smb = smem_u32_of(smem);
    float* red = reinterpret_cast<float*>(smem + OFF_RED);   // [64][4]

    const int kk    = blockIdx.x;
    const int bbase = blockIdx.y * 256;     // this CTA's 256-row batch split
    const int tid   = threadIdx.x;
    const int wid   = tid >> 5;
    const int lane  = tid & 31;

    // ---- one-time: load W_kk fp32, split to bf16 hi/lo tiles ----
    {
        const float4* Wp = reinterpret_cast<const float4*>(W + (size_t)kk * H * HP);
        for (int i = tid; i < H * 32; i += 512) {      // 256 rows x 32 float4
            const int row = i >> 5, c4 = i & 31;
            const float4 v = __ldg(Wp + i);
            const __nv_bfloat16 hx = __float2bfloat16(v.x);
            const __nv_bfloat16 hy = __float2bfloat16(v.y);
            const __nv_bfloat16 hz = __float2bfloat16(v.z);
            const __nv_bfloat16 hw = __float2bfloat16(v.w);
            uint2 hp, lp;
            hp.x = pack_bf16x2(hx, hy);
            hp.y = pack_bf16x2(hz, hw);
            lp.x = pack_bf16x2(__float2bfloat16(v.x - __bfloat162float(hx)),
                               __float2bfloat16(v.y - __bfloat162float(hy)));
            lp.y = pack_bf16x2(__float2bfloat16(v.z - __bfloat162float(hz)),
                               __float2bfloat16(v.w - __bfloat162float(hw)));
            const int dst = row * TSTRIDE + c4 * 8;
            *reinterpret_cast<uint2*>(smem + OFF_BH + dst) = hp;
            *reinterpret_cast<uint2*>(smem + OFF_BL + dst) = lp;
        }
    }

    // ---- A prefetch (cp.async, 64 rows x 16 granules, hi+lo) ----
    auto prefetch = [&](int it) {
        const int s = it & 1;
        const u32 aHi = smb + OFF_AST + s * A_STAGE;
        const u32 aLo = aHi + 64 * TSTRIDE;
        const size_t base = (size_t)(bbase + it * 64) * HP;
        for (int i = tid; i < 64 * 16; i += 512) {
            const int row = i >> 4, g = i & 15;
            const size_t src = base + (size_t)row * HP + g * 8;
            const u32 d = row * TSTRIDE + g * 16;
            cp16(aHi + d, g_x3h + src);
            cp16(aLo + d, g_x3l + src);
        }
    };

    prefetch(0);
    CP_COMMIT();

    const int bgrp = wid & 3;     // 16-row group within the 64-row tile
    const int hgrp = wid >> 2;    // 64-col h group

    // per-lane ldmatrix offsets
    const u32 aOff = (u32)((bgrp * 16 + (lane & 15)) * TSTRIDE + (lane >> 4) * 16);
    const u32 bBase = smb +
        (u32)((hgrp * 64 + ((lane >> 4) << 3) + (lane & 7)) * TSTRIDE
              + (((lane >> 3) & 1) * 16));

    const int gid = lane >> 2;          // 0..7
    const int cp  = (lane & 3) * 2;     // col pair base

    for (int it = 0; it < NIT; it++) {
        if (it + 1 < NIT) {
            prefetch(it + 1);
            CP_COMMIT();
            CP_WAIT(1);
        } else {
            CP_WAIT(0);
        }
        __syncthreads();

        const int s = it & 1;
        const u32 aHi = smb + OFF_AST + s * A_STAGE + aOff;
        const u32 aLo = aHi + 64 * TSTRIDE;

        float acc[8][4];
#pragma unroll
        for (int j = 0; j < 8; j++)
#pragma unroll
            for (int e = 0; e < 4; e++) acc[j][e] = 0.0f;

#pragma unroll
        for (int k = 0; k < 8; k++) {
            const u32 koff = k * 32;
            u32 ah[4], al[4];
            ldsm4(ah, aHi + koff);
            ldsm4(al, aLo + koff);
#pragma unroll
            for (int jp = 0; jp < 4; jp++) {
                u32 bh[4], bl[4];
                ldsm4(bh, bBase + OFF_BH + jp * 16 * TSTRIDE + koff);
                ldsm4(bl, bBase + OFF_BL + jp * 16 * TSTRIDE + koff);
                // A_hi*B_hi + A_hi*B_lo + A_lo*B_hi
                mma_bf16(acc[2 * jp],     ah, bh);
                mma_bf16(acc[2 * jp + 1], ah, bh + 2);
                mma_bf16(acc[2 * jp],     ah, bl);
                mma_bf16(acc[2 * jp + 1], ah, bl + 2);
                mma_bf16(acc[2 * jp],     al, bh);
                mma_bf16(acc[2 * jp + 1], al, bh + 2);
            }
        }

        // ---- epilogue: fold with vec, reduce over h ----
        const int b0 = bbase + it * 64;
        {
            const int rowA = bgrp * 16 + gid;
            const int rowB = rowA + 8;
            const float* vA = vec + (size_t)(b0 + rowA) * H + hgrp * 64 + cp;
            const float* vB = vec + (size_t)(b0 + rowB) * H + hgrp * 64 + cp;
            float pA = 0.f, pB = 0.f;
#pragma unroll
            for (int j = 0; j < 8; j++) {
                const float2 a2 = __ldg(reinterpret_cast<const float2*>(vA + j * 8));
                const float2 b2 = __ldg(reinterpret_cast<const float2*>(vB + j * 8));
                pA = fmaf(acc[j][0], a2.x, fmaf(acc[j][1], a2.y, pA));
                pB = fmaf(acc[j][2], b2.x, fmaf(acc[j][3], b2.y, pB));
            }
            pA += __shfl_xor_sync(0xffffffffu, pA, 1);
            pA += __shfl_xor_sync(0xffffffffu, pA, 2);
            pB += __shfl_xor_sync(0xffffffffu, pB, 1);
            pB += __shfl_xor_sync(0xffffffffu, pB, 2);
            if ((lane & 3) == 0) {
                red[rowA * 4 + hgrp] = pA;
                red[rowB * 4 + hgrp] = pB;
            }
        }
        __syncthreads();

        if (tid < 64) {
            float sv = red[tid * 4 + 0] + red[tid * 4 + 1]
                     + red[tid * 4 + 2] + red[tid * 4 + 3];
            if (APPLY_TANH) sv = tanhf(sv);
            outp[(size_t)(b0 + tid) * H + kk] = sv;
        }
    }
}

// ---------------------------------------------------------------------------
extern "C" void kernel_launch(void* const* d_in, const int* in_sizes, int n_in,
                              void* d_out, int out_size) {
    const float* h0  = (const float*)d_in[0];
    const float* ht  = (const float*)d_in[1];
    const float* msg = (const float*)d_in[2];
    const float* c   = (const float*)d_in[3];
    const float* fc1 = (const float*)d_in[4];
    const float* fc2 = (const float*)d_in[5];
    const float* fc3 = (const float*)d_in[6];
    const float* fc4 = (const float*)d_in[7];
    float* out = (float*)d_out;

    cudaFuncSetAttribute((const void*)hyper_mma_kernel<true>,
                         cudaFuncAttributeMaxDynamicSharedMemorySize, SMEM_TOTAL);
    cudaFuncSetAttribute((const void*)hyper_mma_kernel<false>,
                         cudaFuncAttributeMaxDynamicSharedMemorySize, SMEM_TOTAL);

    void* p_g1 = nullptr;
    cudaGetSymbolAddress(&p_g1, g_g1);

    // 1) MLP head -> x3 hi/lo
    mlp_head_kernel<<<B_TOTAL / 4, 128>>>(h0, ht, c, fc1, fc2, fc3);

    // 2) phase A: g1 = tanh( fold(msg, x3 @ W1^T) )
    hyper_mma_kernel<true><<<dim3(H, 4), 512, SMEM_TOTAL>>>(
        fc4, msg, (float*)p_g1);

    // 3) phase B: out = fold(g1, x3 @ W2^T)
    hyper_mma_kernel<false><<<dim3(H, 4), 512, SMEM_TOTAL>>>(
        fc4 + (size_t)H * H * HP, (const float*)p_g1, out);
}